// round 3
// baseline (speedup 1.0000x reference)
#include <cuda_runtime.h>
#include <cuda_bf16.h>
#include <cstdint>

#define EMB    512
#define HID    512
#define NCLASS 50257
#define BATCH  64
#define STEPS  256
#define FOURH  2048

// ---------------- scratch (device globals; no mallocs allowed) ---------------
__device__ float    g_xw[STEPS * BATCH * FOURH];   // 128 MiB precomputed input proj
__device__ float    g_h[2 * BATCH * HID];          // double-buffered hidden state
__device__ float    g_bsum[FOURH];                 // bi + bh
// barrier words on SEPARATE 128B L2 lines (atomics + polls must not share a line)
__device__ __align__(128) unsigned g_barc[32];     // monotonic arrival counter
__device__ __align__(128) unsigned g_barp[32];     // monotonic phase

// ---------------- packed f32x2 helpers (sm_103a) ------------------------------
__device__ __forceinline__ unsigned long long pack2(float x, float y) {
    unsigned long long r;
    asm("mov.b64 %0, {%1, %2};" : "=l"(r) : "f"(x), "f"(y));
    return r;
}
__device__ __forceinline__ void fma2(unsigned long long& acc,
                                     unsigned long long a, unsigned long long b) {
    asm("fma.rn.f32x2 %0, %1, %2, %0;" : "+l"(acc) : "l"(a), "l"(b));
}
__device__ __forceinline__ float2 unpack2(unsigned long long v) {
    float2 f;
    asm("mov.b64 {%0, %1}, %2;" : "=f"(f.x), "=f"(f.y) : "l"(v));
    return f;
}
__device__ __forceinline__ float hsum2(unsigned long long v) {
    float2 f = unpack2(v);
    return f.x + f.y;
}
__device__ __forceinline__ float sigmoidf_(float x) {
    return 1.0f / (1.0f + expf(-x));
}
__device__ __forceinline__ unsigned long long f4lo(const float4& v) {
    return ((const unsigned long long*)&v)[0];
}
__device__ __forceinline__ unsigned long long f4hi(const float4& v) {
    return ((const unsigned long long*)&v)[1];
}

// ---------------- grid barrier (monotonic phase, release/acquire) -------------
__device__ __forceinline__ void grid_barrier(unsigned nct, unsigned target) {
    __syncthreads();
    if (threadIdx.x == 0) {
        __threadfence();  // make whole-CTA stores cumulative into the release
        unsigned old;
        asm volatile("atom.release.gpu.global.add.u32 %0, [%1], 1;"
                     : "=r"(old) : "l"(&g_barc[0]) : "memory");
        if (old + 1 == target * nct) {
            asm volatile("st.release.gpu.global.u32 [%0], %1;"
                         :: "l"(&g_barp[0]), "r"(target) : "memory");
        } else {
            unsigned cur;
            do {
                asm volatile("ld.acquire.gpu.global.u32 %0, [%1];"
                             : "=r"(cur) : "l"(&g_barp[0]) : "memory");
            } while (cur < target);
        }
    }
    __syncthreads();
}

// ---------------- kernel 0: prep (bsum = bi + bh, zero h, reset barrier) ------
__global__ void prep_kernel(const float* __restrict__ bi, const float* __restrict__ bh) {
    int i = blockIdx.x * blockDim.x + threadIdx.x;
    int stride = gridDim.x * blockDim.x;
    if (i == 0) { g_barc[0] = 0u; g_barp[0] = 0u; }
    if (i < FOURH) g_bsum[i] = bi[i] + bh[i];
    for (int j = i; j < 2 * BATCH * HID; j += stride) g_h[j] = 0.0f;
}

// ---------------- kernel 1: xw = gather(emb, X) @ Wi + bsum -------------------
// C[16384, 2048], K = 512. BM=BN=128, BK=16, 256 threads, 8x8 microtile, f32x2.
__global__ __launch_bounds__(256, 2) void xw_gemm_kernel(
    const int* __restrict__ X, const float* __restrict__ emb,
    const float* __restrict__ Wi) {
    __shared__ float As[16][132];  // A^T tile: As[k][m]
    __shared__ float Bs[16][132];  // Bs[k][n]
    __shared__ int   tok[128];

    const int tid = threadIdx.x;
    const int m0 = blockIdx.y * 128;
    const int n0 = blockIdx.x * 128;
    const int tm = tid >> 4, tn = tid & 15;

    if (tid < 128) {
        int m = m0 + tid;
        int b = m & 63, t = m >> 6;
        tok[tid] = X[b * STEPS + t];
    }

    unsigned long long acc[8][4];
#pragma unroll
    for (int i = 0; i < 8; ++i)
#pragma unroll
        for (int j = 0; j < 4; ++j) acc[i][j] = 0ull;

    for (int kt = 0; kt < EMB; kt += 16) {
        __syncthreads();
#pragma unroll
        for (int q = 0; q < 2; ++q) {
            int id = tid + q * 256;           // 0..511 float4 slots
            int row = id >> 2, c4 = id & 3;
            const float4 v = *(const float4*)(emb + (size_t)tok[row] * EMB + kt + c4 * 4);
            As[c4 * 4 + 0][row] = v.x;
            As[c4 * 4 + 1][row] = v.y;
            As[c4 * 4 + 2][row] = v.z;
            As[c4 * 4 + 3][row] = v.w;
        }
#pragma unroll
        for (int q = 0; q < 2; ++q) {
            int id = tid + q * 256;
            int k = id >> 5, c4 = id & 31;
            const float4 v = *(const float4*)(Wi + (size_t)(kt + k) * FOURH + n0 + c4 * 4);
            *(float4*)&Bs[k][c4 * 4] = v;
        }
        __syncthreads();
#pragma unroll
        for (int kk = 0; kk < 16; ++kk) {
            float4 a0 = *(const float4*)&As[kk][tm * 8];
            float4 a1 = *(const float4*)&As[kk][tm * 8 + 4];
            float4 b0 = *(const float4*)&Bs[kk][tn * 8];
            float4 b1 = *(const float4*)&Bs[kk][tn * 8 + 4];
            unsigned long long bp0 = ((const unsigned long long*)&b0)[0];
            unsigned long long bp1 = ((const unsigned long long*)&b0)[1];
            unsigned long long bp2 = ((const unsigned long long*)&b1)[0];
            unsigned long long bp3 = ((const unsigned long long*)&b1)[1];
            float av[8] = {a0.x, a0.y, a0.z, a0.w, a1.x, a1.y, a1.z, a1.w};
#pragma unroll
            for (int i = 0; i < 8; ++i) {
                unsigned long long ad = pack2(av[i], av[i]);
                fma2(acc[i][0], ad, bp0);
                fma2(acc[i][1], ad, bp1);
                fma2(acc[i][2], ad, bp2);
                fma2(acc[i][3], ad, bp3);
            }
        }
    }

    const float4 bs0 = *(const float4*)&g_bsum[n0 + tn * 8];
    const float4 bs1 = *(const float4*)&g_bsum[n0 + tn * 8 + 4];
    const float bsv[8] = {bs0.x, bs0.y, bs0.z, bs0.w, bs1.x, bs1.y, bs1.z, bs1.w};
#pragma unroll
    for (int i = 0; i < 8; ++i) {
        int m = m0 + tm * 8 + i;
        float o[8];
#pragma unroll
        for (int j = 0; j < 4; ++j) {
            float2 v = unpack2(acc[i][j]);
            o[2 * j] = v.x + bsv[2 * j];
            o[2 * j + 1] = v.y + bsv[2 * j + 1];
        }
        float* orow = g_xw + (size_t)m * FOURH + n0 + tn * 8;
        *(float4*)&orow[0] = make_float4(o[0], o[1], o[2], o[3]);
        *(float4*)&orow[4] = make_float4(o[4], o[5], o[6], o[7]);
    }
}

// ---------------- kernel 2: persistent LSTM recurrence ------------------------
// 128 CTAs x 512 thr (4 warps/SMSP). Thread owns 2 cells (col-pair x 1 batch).
// Double-buffered 64-wide h tiles; xw prefetched one step ahead.
__global__ __launch_bounds__(512, 1) void lstm_kernel(const float* __restrict__ Wh) {
    __shared__ __align__(16) float swE[8][516];   // even gate-cols (stride: 4-bank skew)
    __shared__ __align__(16) float swO[8][516];   // odd  gate-cols
    __shared__ __align__(16) float sh[2][64][68]; // double-buffered h k-tiles
    __shared__ float spre[16][65];                // pre-activations [c][b]
    __shared__ float sc[256];                     // cell state [b*4+u]

    const int tid = threadIdx.x;
    const int cta = blockIdx.x;
    const unsigned nct = gridDim.x;

    // one-time load of the 16 Wh columns this CTA owns (col = g*512 + cta*4 + u)
    for (int i = tid; i < 16 * HID; i += 512) {
        int c = i >> 9, k = i & 511;
        int g = c >> 2, u = c & 3;
        float w = Wh[(size_t)k * FOURH + g * HID + cta * 4 + u];
        if (c & 1) swO[c >> 1][k] = w;
        else       swE[c >> 1][k] = w;
    }
    if (tid < 256) sc[tid] = 0.0f;

    const int cp = tid & 7;          // col-pair 0..7
    const int b  = tid >> 3;         // batch 0..63
    const int c0 = 2 * cp, c1 = c0 + 1;
    const int gc0 = (c0 >> 2) * HID + cta * 4 + (c0 & 3);
    const int gc1 = (c1 >> 2) * HID + cta * 4 + (c1 & 3);

    // cooperative-load mapping: 64 rows x 64 k = 1024 float4; 2 per thread
    const int lrow = tid >> 4;        // 0..31 (+32)
    const int lcol = (tid & 15) * 4;  // float offset within tile

    const int upd_u = tid & 3, upd_b = tid >> 2;  // valid for tid < 256

    // prefetch xw for step 0
    float x0 = __ldcs(&g_xw[b * FOURH + gc0]);
    float x1 = __ldcs(&g_xw[b * FOURH + gc1]);

    __syncthreads();

    for (int t = 0; t < STEPS; ++t) {
        const float* hin  = g_h + (t & 1) * BATCH * HID;
        float*       hout = g_h + ((t + 1) & 1) * BATCH * HID;

        unsigned long long a0a = 0, a0b = 0, a1a = 0, a1b = 0;

        // tile 0 -> sh[0], prefetch tile 1 into regs
        float4 p0 = __ldcg((const float4*)(hin + (lrow + 0)  * HID + lcol));
        float4 p1 = __ldcg((const float4*)(hin + (lrow + 32) * HID + lcol));
        *(float4*)&sh[0][lrow + 0][lcol]  = p0;
        *(float4*)&sh[0][lrow + 32][lcol] = p1;
        p0 = __ldcg((const float4*)(hin + (lrow + 0)  * HID + 64 + lcol));
        p1 = __ldcg((const float4*)(hin + (lrow + 32) * HID + 64 + lcol));
        __syncthreads();

        for (int kt8 = 0; kt8 < 8; ++kt8) {
            const float* hrow  = &sh[kt8 & 1][b][0];
            const float* wrow0 = &swE[cp][kt8 * 64];
            const float* wrow1 = &swO[cp][kt8 * 64];
#pragma unroll
            for (int kk = 0; kk < 64; kk += 4) {
                float4 hv = *(const float4*)(hrow  + kk);
                float4 w0 = *(const float4*)(wrow0 + kk);
                float4 w1 = *(const float4*)(wrow1 + kk);
                unsigned long long ha = f4lo(hv), hb = f4hi(hv);
                fma2(a0a, ha, f4lo(w0)); fma2(a0b, hb, f4hi(w0));
                fma2(a1a, ha, f4lo(w1)); fma2(a1b, hb, f4hi(w1));
            }
            if (kt8 < 7) {
                int nb = (kt8 + 1) & 1;
                *(float4*)&sh[nb][lrow + 0][lcol]  = p0;
                *(float4*)&sh[nb][lrow + 32][lcol] = p1;
                if (kt8 < 6) {
                    int ko = (kt8 + 2) * 64;
                    p0 = __ldcg((const float4*)(hin + (lrow + 0)  * HID + ko + lcol));
                    p1 = __ldcg((const float4*)(hin + (lrow + 32) * HID + ko + lcol));
                }
                __syncthreads();
            }
        }

        spre[c0][b] = hsum2(a0a) + hsum2(a0b) + x0;
        spre[c1][b] = hsum2(a1a) + hsum2(a1b) + x1;

        // prefetch xw for step t+1 (hidden behind barrier + next GEMM)
        {
            int tn = (t + 1 < STEPS) ? (t + 1) : 0;
            const float* xwn = g_xw + (size_t)tn * BATCH * FOURH;
            x0 = __ldcs(&xwn[b * FOURH + gc0]);
            x1 = __ldcs(&xwn[b * FOURH + gc1]);
        }
        __syncthreads();

        // cell update: thread -> (b = tid>>2, u = tid&3), tid < 256
        if (tid < 256) {
            float pi = spre[0  + upd_u][upd_b];
            float pf = spre[4  + upd_u][upd_b];
            float pg = spre[8  + upd_u][upd_b];
            float po = spre[12 + upd_u][upd_b];
            float ig = sigmoidf_(pi);
            float fg = sigmoidf_(pf);
            float gg = tanhf(pg);
            float og = sigmoidf_(po);
            float cc = fg * sc[tid] + ig * gg;
            sc[tid] = cc;
            float hh = og * tanhf(cc);
            __stcg(&hout[upd_b * HID + cta * 4 + upd_u], hh);
        }
        grid_barrier(nct, (unsigned)(t + 1));
    }
}

// ---------------- kernel 3: out = h_final @ Wout^T + bout ---------------------
__global__ __launch_bounds__(256, 2) void outproj_kernel(
    const float* __restrict__ Wout, const float* __restrict__ bout,
    float* __restrict__ out) {
    __shared__ float As[16][132];  // Wout^T tile: As[k][n_local]
    __shared__ float Bs[16][68];   // h^T tile:   Bs[k][b]

    const int tid = threadIdx.x;
    const int n0 = blockIdx.x * 128;
    const int tn = tid & 15, tb = tid >> 4;
    const float* h = g_h;  // final h lives in buffer 0 (STEPS even)

    unsigned long long acc[8][2];
#pragma unroll
    for (int i = 0; i < 8; ++i) { acc[i][0] = 0ull; acc[i][1] = 0ull; }

    for (int kt = 0; kt < HID; kt += 16) {
        __syncthreads();
#pragma unroll
        for (int q = 0; q < 2; ++q) {
            int id = tid + q * 256;
            int row = id >> 2, c4 = id & 3;
            int n = n0 + row;
            float4 v = make_float4(0.f, 0.f, 0.f, 0.f);
            if (n < NCLASS) v = *(const float4*)(Wout + (size_t)n * HID + kt + c4 * 4);
            As[c4 * 4 + 0][row] = v.x;
            As[c4 * 4 + 1][row] = v.y;
            As[c4 * 4 + 2][row] = v.z;
            As[c4 * 4 + 3][row] = v.w;
        }
#pragma unroll
        for (int q = 0; q < 4; ++q) {
            int id = tid + q * 256;   // 0..1023
            int b = id >> 4, k = id & 15;
            Bs[k][b] = h[b * HID + kt + k];
        }
        __syncthreads();
#pragma unroll
        for (int kk = 0; kk < 16; ++kk) {
            float4 a0 = *(const float4*)&As[kk][tn * 8];
            float4 a1 = *(const float4*)&As[kk][tn * 8 + 4];
            float4 bv = *(const float4*)&Bs[kk][tb * 4];
            unsigned long long bp0 = ((const unsigned long long*)&bv)[0];
            unsigned long long bp1 = ((const unsigned long long*)&bv)[1];
            float av[8] = {a0.x, a0.y, a0.z, a0.w, a1.x, a1.y, a1.z, a1.w};
#pragma unroll
            for (int i = 0; i < 8; ++i) {
                unsigned long long ad = pack2(av[i], av[i]);
                fma2(acc[i][0], ad, bp0);
                fma2(acc[i][1], ad, bp1);
            }
        }
    }

#pragma unroll
    for (int i = 0; i < 8; ++i) {
        int n = n0 + tn * 8 + i;
        if (n >= NCLASS) continue;
        float bo = bout[n];
        float2 v0 = unpack2(acc[i][0]);
        float2 v1 = unpack2(acc[i][1]);
        out[(size_t)(tb * 4 + 0) * NCLASS + n] = v0.x + bo;
        out[(size_t)(tb * 4 + 1) * NCLASS + n] = v0.y + bo;
        out[(size_t)(tb * 4 + 2) * NCLASS + n] = v1.x + bo;
        out[(size_t)(tb * 4 + 3) * NCLASS + n] = v1.y + bo;
    }
}

// ---------------- launch --------------------------------------------------------
extern "C" void kernel_launch(void* const* d_in, const int* in_sizes, int n_in,
                              void* d_out, int out_size) {
    const int*   X    = (const int*)d_in[0];
    const float* emb  = (const float*)d_in[1];
    const float* Wi   = (const float*)d_in[2];
    const float* Wh   = (const float*)d_in[3];
    const float* bi   = (const float*)d_in[4];
    const float* bh   = (const float*)d_in[5];
    // d_in[6..9]: layer-2 params — provably unused by the reference output
    const float* Wout = (const float*)d_in[10];
    const float* bout = (const float*)d_in[11];
    float* out = (float*)d_out;

    prep_kernel<<<64, 256>>>(bi, bh);
    xw_gemm_kernel<<<dim3(FOURH / 128, (STEPS * BATCH) / 128), 256>>>(X, emb, Wi);
    lstm_kernel<<<128, 512>>>(Wh);
    outproj_kernel<<<(NCLASS + 127) / 128, 256>>>(Wout, bout, out);
}

// round 4
// speedup vs baseline: 1.2148x; 1.2148x over previous
#include <cuda_runtime.h>
#include <cuda_bf16.h>
#include <cstdint>

#define EMB    512
#define HID    512
#define NCLASS 50257
#define BATCH  64
#define STEPS  256
#define FOURH  2048

// ---------------- scratch (device globals; no mallocs allowed) ---------------
__device__ float    g_xw[STEPS * BATCH * FOURH];   // 128 MiB precomputed input proj
__device__ float    g_h[2 * BATCH * HID];          // double-buffered hidden state
__device__ float    g_bsum[FOURH];                 // bi + bh
// hierarchical barrier: 16 L1 counters + 1 L2 counter + phase, each on own 128B line
__device__ __align__(128) unsigned g_barc1[16 * 32];
__device__ __align__(128) unsigned g_barc2[32];
__device__ __align__(128) unsigned g_barp[32];

// ---------------- packed f32x2 helpers (sm_103a) ------------------------------
__device__ __forceinline__ unsigned long long pack2(float x, float y) {
    unsigned long long r;
    asm("mov.b64 %0, {%1, %2};" : "=l"(r) : "f"(x), "f"(y));
    return r;
}
__device__ __forceinline__ void fma2(unsigned long long& acc,
                                     unsigned long long a, unsigned long long b) {
    asm("fma.rn.f32x2 %0, %1, %2, %0;" : "+l"(acc) : "l"(a), "l"(b));
}
__device__ __forceinline__ float2 unpack2(unsigned long long v) {
    float2 f;
    asm("mov.b64 {%0, %1}, %2;" : "=f"(f.x), "=f"(f.y) : "l"(v));
    return f;
}
__device__ __forceinline__ float hsum2(unsigned long long v) {
    float2 f = unpack2(v);
    return f.x + f.y;
}
__device__ __forceinline__ float sigmoidf_(float x) {
    return 1.0f / (1.0f + expf(-x));
}
__device__ __forceinline__ unsigned long long f4lo(const float4& v) {
    return ((const unsigned long long*)&v)[0];
}
__device__ __forceinline__ unsigned long long f4hi(const float4& v) {
    return ((const unsigned long long*)&v)[1];
}

// ---------------- hierarchical grid barrier (128 CTAs = 16 groups x 8) --------
__device__ __forceinline__ void grid_barrier(unsigned target) {
    __syncthreads();
    if (threadIdx.x == 0) {
        __threadfence();  // make this CTA's stores cumulative into the release-add
        unsigned grp = blockIdx.x & 15u;
        unsigned old;
        asm volatile("atom.release.gpu.global.add.u32 %0, [%1], 1;"
                     : "=r"(old) : "l"(&g_barc1[grp * 32]) : "memory");
        if (old + 1u == target * 8u) {          // last of this 8-CTA group
            unsigned old2;
            asm volatile("atom.acq_rel.gpu.global.add.u32 %0, [%1], 1;"
                         : "=r"(old2) : "l"(&g_barc2[0]) : "memory");
            if (old2 + 1u == target * 16u) {    // last group overall -> release
                asm volatile("st.release.gpu.global.u32 [%0], %1;"
                             :: "l"(&g_barp[0]), "r"(target) : "memory");
            }
        }
        unsigned cur;
        do {
            asm volatile("ld.acquire.gpu.global.u32 %0, [%1];"
                         : "=r"(cur) : "l"(&g_barp[0]) : "memory");
        } while (cur < target);
    }
    __syncthreads();
}

// ---------------- kernel 0: prep (bsum = bi + bh, zero h, reset barrier) ------
__global__ void prep_kernel(const float* __restrict__ bi, const float* __restrict__ bh) {
    int i = blockIdx.x * blockDim.x + threadIdx.x;
    int stride = gridDim.x * blockDim.x;
    if (i < 16 * 32) g_barc1[i] = 0u;
    if (i < 32) { g_barc2[i] = 0u; g_barp[i] = 0u; }
    if (i < FOURH) g_bsum[i] = bi[i] + bh[i];
    for (int j = i; j < 2 * BATCH * HID; j += stride) g_h[j] = 0.0f;
}

// ---------------- kernel 1: xw = gather(emb, X) @ Wi + bsum -------------------
// C[16384, 2048], K=512. BM=BN=128, BK=16, 256 thr, 8x8 microtile, f32x2,
// register-prefetch double buffer, one sync per k-tile.
__global__ __launch_bounds__(256, 2) void xw_gemm_kernel(
    const int* __restrict__ X, const float* __restrict__ emb,
    const float* __restrict__ Wi) {
    __shared__ float As[2][16][132];  // A^T tile: As[buf][k][m]
    __shared__ float Bs[2][16][132];  // Bs[buf][k][n]
    __shared__ int   tok[128];

    const int tid = threadIdx.x;
    const int m0 = blockIdx.y * 128;
    const int n0 = blockIdx.x * 128;
    const int tm = tid >> 4, tn = tid & 15;

    // loader mappings
    const int arow0 = tid >> 2,            ac4_0 = tid & 3;
    const int arow1 = (tid + 256) >> 2,    ac4_1 = (tid + 256) & 3;
    const int bk0   = tid >> 5,            bc4_0 = tid & 31;
    const int bk1   = (tid + 256) >> 5,    bc4_1 = (tid + 256) & 31;

    if (tid < 128) {
        int m = m0 + tid;
        int b = m & 63, t = m >> 6;
        tok[tid] = X[b * STEPS + t];
    }
    __syncthreads();

    unsigned long long acc[8][4];
#pragma unroll
    for (int i = 0; i < 8; ++i)
#pragma unroll
        for (int j = 0; j < 4; ++j) acc[i][j] = 0ull;

    // preload k-tile 0 into regs
    float4 pa0 = *(const float4*)(emb + (size_t)tok[arow0] * EMB + ac4_0 * 4);
    float4 pa1 = *(const float4*)(emb + (size_t)tok[arow1] * EMB + ac4_1 * 4);
    float4 pb0 = *(const float4*)(Wi + (size_t)bk0 * FOURH + n0 + bc4_0 * 4);
    float4 pb1 = *(const float4*)(Wi + (size_t)bk1 * FOURH + n0 + bc4_1 * 4);

    int cur = 0;
    for (int kt = 0; kt < EMB; kt += 16) {
        // store prefetched tile into smem[cur]
        As[cur][ac4_0 * 4 + 0][arow0] = pa0.x;
        As[cur][ac4_0 * 4 + 1][arow0] = pa0.y;
        As[cur][ac4_0 * 4 + 2][arow0] = pa0.z;
        As[cur][ac4_0 * 4 + 3][arow0] = pa0.w;
        As[cur][ac4_1 * 4 + 0][arow1] = pa1.x;
        As[cur][ac4_1 * 4 + 1][arow1] = pa1.y;
        As[cur][ac4_1 * 4 + 2][arow1] = pa1.z;
        As[cur][ac4_1 * 4 + 3][arow1] = pa1.w;
        *(float4*)&Bs[cur][bk0][bc4_0 * 4] = pb0;
        *(float4*)&Bs[cur][bk1][bc4_1 * 4] = pb1;
        // prefetch next tile
        if (kt + 16 < EMB) {
            int kn = kt + 16;
            pa0 = *(const float4*)(emb + (size_t)tok[arow0] * EMB + kn + ac4_0 * 4);
            pa1 = *(const float4*)(emb + (size_t)tok[arow1] * EMB + kn + ac4_1 * 4);
            pb0 = *(const float4*)(Wi + (size_t)(kn + bk0) * FOURH + n0 + bc4_0 * 4);
            pb1 = *(const float4*)(Wi + (size_t)(kn + bk1) * FOURH + n0 + bc4_1 * 4);
        }
        __syncthreads();
#pragma unroll
        for (int kk = 0; kk < 16; ++kk) {
            float4 a0 = *(const float4*)&As[cur][kk][tm * 8];
            float4 a1 = *(const float4*)&As[cur][kk][tm * 8 + 4];
            float4 b0 = *(const float4*)&Bs[cur][kk][tn * 8];
            float4 b1 = *(const float4*)&Bs[cur][kk][tn * 8 + 4];
            unsigned long long bp0 = f4lo(b0), bp1 = f4hi(b0);
            unsigned long long bp2 = f4lo(b1), bp3 = f4hi(b1);
            float av[8] = {a0.x, a0.y, a0.z, a0.w, a1.x, a1.y, a1.z, a1.w};
#pragma unroll
            for (int i = 0; i < 8; ++i) {
                unsigned long long ad = pack2(av[i], av[i]);
                fma2(acc[i][0], ad, bp0);
                fma2(acc[i][1], ad, bp1);
                fma2(acc[i][2], ad, bp2);
                fma2(acc[i][3], ad, bp3);
            }
        }
        cur ^= 1;
    }

    const float4 bs0 = *(const float4*)&g_bsum[n0 + tn * 8];
    const float4 bs1 = *(const float4*)&g_bsum[n0 + tn * 8 + 4];
    const float bsv[8] = {bs0.x, bs0.y, bs0.z, bs0.w, bs1.x, bs1.y, bs1.z, bs1.w};
#pragma unroll
    for (int i = 0; i < 8; ++i) {
        int m = m0 + tm * 8 + i;
        float o[8];
#pragma unroll
        for (int j = 0; j < 4; ++j) {
            float2 v = unpack2(acc[i][j]);
            o[2 * j] = v.x + bsv[2 * j];
            o[2 * j + 1] = v.y + bsv[2 * j + 1];
        }
        float* orow = g_xw + (size_t)m * FOURH + n0 + tn * 8;
        *(float4*)&orow[0] = make_float4(o[0], o[1], o[2], o[3]);
        *(float4*)&orow[4] = make_float4(o[4], o[5], o[6], o[7]);
    }
}

// ---------------- kernel 2: persistent LSTM recurrence (R2 body) --------------
// 128 CTAs x 256 thr. CTA owns 4 hidden units (16 gate cols). One grid barrier/step.
__global__ __launch_bounds__(256, 1) void lstm_kernel(const float* __restrict__ Wh) {
    __shared__ __align__(16) float swE[8][516];   // even gate-cols (stride: 4-bank skew)
    __shared__ __align__(16) float swO[8][516];   // odd  gate-cols
    __shared__ __align__(16) float sh[2][64][68]; // double-buffered h k-tiles
    __shared__ float spre[16][65];                // pre-activations [c][b]
    __shared__ float sc[256];                     // cell state [b*4+u]

    const int tid = threadIdx.x;
    const int cta = blockIdx.x;

    // one-time load of the 16 Wh columns this CTA owns (col = g*512 + cta*4 + u)
    for (int i = tid; i < 16 * HID; i += 256) {
        int c = i >> 9, k = i & 511;
        int g = c >> 2, u = c & 3;
        float w = Wh[(size_t)k * FOURH + g * HID + cta * 4 + u];
        if (c & 1) swO[c >> 1][k] = w;
        else       swE[c >> 1][k] = w;
    }
    sc[tid] = 0.0f;

    const int cp = tid & 7, bp = tid >> 3;
    const int b0 = 2 * bp, b1 = b0 + 1;
    const int c0 = 2 * cp, c1 = c0 + 1;
    const int gc0 = (c0 >> 2) * HID + cta * 4 + (c0 & 3);
    const int gc1 = (c1 >> 2) * HID + cta * 4 + (c1 & 3);

    // cooperative-load mapping: 64 rows x 64 k floats = 1024 float4; 4 per thread
    const int lrow = tid >> 4;        // 0..15 (+16q)
    const int lcol = (tid & 15) * 4;  // float offset within tile

    const int upd_u = tid & 3, upd_b = tid >> 2;

    __syncthreads();

    for (int t = 0; t < STEPS; ++t) {
        const float* hin  = g_h + (t & 1) * BATCH * HID;
        float*       hout = g_h + ((t + 1) & 1) * BATCH * HID;
        const float* xwt  = g_xw + (size_t)t * BATCH * FOURH;

        // prefetch xw gate biases for this step (DRAM; hidden behind the GEMM)
        float x00 = __ldcs(&xwt[b0 * FOURH + gc0]);
        float x01 = __ldcs(&xwt[b0 * FOURH + gc1]);
        float x10 = __ldcs(&xwt[b1 * FOURH + gc0]);
        float x11 = __ldcs(&xwt[b1 * FOURH + gc1]);

        unsigned long long a00a = 0, a00b = 0, a01a = 0, a01b = 0;
        unsigned long long a10a = 0, a10b = 0, a11a = 0, a11b = 0;

        // tile 0 -> sh[0], prefetch tile 1 into regs
        float4 p0 = __ldcg((const float4*)(hin + (lrow + 0)  * HID + lcol));
        float4 p1 = __ldcg((const float4*)(hin + (lrow + 16) * HID + lcol));
        float4 p2 = __ldcg((const float4*)(hin + (lrow + 32) * HID + lcol));
        float4 p3 = __ldcg((const float4*)(hin + (lrow + 48) * HID + lcol));
        *(float4*)&sh[0][lrow + 0][lcol]  = p0;
        *(float4*)&sh[0][lrow + 16][lcol] = p1;
        *(float4*)&sh[0][lrow + 32][lcol] = p2;
        *(float4*)&sh[0][lrow + 48][lcol] = p3;
        p0 = __ldcg((const float4*)(hin + (lrow + 0)  * HID + 64 + lcol));
        p1 = __ldcg((const float4*)(hin + (lrow + 16) * HID + 64 + lcol));
        p2 = __ldcg((const float4*)(hin + (lrow + 32) * HID + 64 + lcol));
        p3 = __ldcg((const float4*)(hin + (lrow + 48) * HID + 64 + lcol));
        __syncthreads();

        for (int kt8 = 0; kt8 < 8; ++kt8) {
            const float* shb = &sh[kt8 & 1][0][0];
            const float* hrow0 = shb + b0 * 68;
            const float* hrow1 = shb + b1 * 68;
            const float* wrow0 = &swE[cp][kt8 * 64];
            const float* wrow1 = &swO[cp][kt8 * 64];
#pragma unroll
            for (int kk = 0; kk < 64; kk += 4) {
                float4 h0 = *(const float4*)(hrow0 + kk);
                float4 h1 = *(const float4*)(hrow1 + kk);
                float4 w0 = *(const float4*)(wrow0 + kk);
                float4 w1 = *(const float4*)(wrow1 + kk);
                unsigned long long h0a = f4lo(h0), h0b = f4hi(h0);
                unsigned long long h1a = f4lo(h1), h1b = f4hi(h1);
                unsigned long long w0a = f4lo(w0), w0b = f4hi(w0);
                unsigned long long w1a = f4lo(w1), w1b = f4hi(w1);
                fma2(a00a, h0a, w0a); fma2(a00b, h0b, w0b);
                fma2(a01a, h0a, w1a); fma2(a01b, h0b, w1b);
                fma2(a10a, h1a, w0a); fma2(a10b, h1b, w0b);
                fma2(a11a, h1a, w1a); fma2(a11b, h1b, w1b);
            }
            if (kt8 < 7) {
                int nb = (kt8 + 1) & 1;
                *(float4*)&sh[nb][lrow + 0][lcol]  = p0;
                *(float4*)&sh[nb][lrow + 16][lcol] = p1;
                *(float4*)&sh[nb][lrow + 32][lcol] = p2;
                *(float4*)&sh[nb][lrow + 48][lcol] = p3;
                if (kt8 < 6) {
                    int ko = (kt8 + 2) * 64;
                    p0 = __ldcg((const float4*)(hin + (lrow + 0)  * HID + ko + lcol));
                    p1 = __ldcg((const float4*)(hin + (lrow + 16) * HID + ko + lcol));
                    p2 = __ldcg((const float4*)(hin + (lrow + 32) * HID + ko + lcol));
                    p3 = __ldcg((const float4*)(hin + (lrow + 48) * HID + ko + lcol));
                }
                __syncthreads();
            }
        }

        spre[c0][b0] = hsum2(a00a) + hsum2(a00b) + x00;
        spre[c1][b0] = hsum2(a01a) + hsum2(a01b) + x01;
        spre[c0][b1] = hsum2(a10a) + hsum2(a10b) + x10;
        spre[c1][b1] = hsum2(a11a) + hsum2(a11b) + x11;
        __syncthreads();

        // cell update: thread -> (b = tid>>2, u = tid&3)
        {
            float pi = spre[0  + upd_u][upd_b];
            float pf = spre[4  + upd_u][upd_b];
            float pg = spre[8  + upd_u][upd_b];
            float po = spre[12 + upd_u][upd_b];
            float ig = sigmoidf_(pi);
            float fg = sigmoidf_(pf);
            float gg = tanhf(pg);
            float og = sigmoidf_(po);
            float cc = fg * sc[tid] + ig * gg;
            sc[tid] = cc;
            float hh = og * tanhf(cc);
            __stcg(&hout[upd_b * HID + cta * 4 + upd_u], hh);
        }
        grid_barrier((unsigned)(t + 1));
    }
}

// ---------------- kernel 3: out = h_final @ Wout^T + bout ---------------------
// Register-prefetch double buffer, one sync per k-tile.
__global__ __launch_bounds__(256, 2) void outproj_kernel(
    const float* __restrict__ Wout, const float* __restrict__ bout,
    float* __restrict__ out) {
    __shared__ float As[2][16][132];  // Wout^T tile: As[buf][k][n_local]
    __shared__ float Bs[2][16][68];   // h^T tile:   Bs[buf][k][b]

    const int tid = threadIdx.x;
    const int n0 = blockIdx.x * 128;
    const int tn = tid & 15, tb = tid >> 4;
    const float* h = g_h;  // final h lives in buffer 0 (STEPS even)

    const int arow0 = tid >> 2,         ac4_0 = tid & 3;
    const int arow1 = (tid + 256) >> 2, ac4_1 = (tid + 256) & 3;

    unsigned long long acc[8][2];
#pragma unroll
    for (int i = 0; i < 8; ++i) { acc[i][0] = 0ull; acc[i][1] = 0ull; }

    // preload tile 0
    float4 pa0 = make_float4(0.f, 0.f, 0.f, 0.f), pa1 = pa0;
    if (n0 + arow0 < NCLASS) pa0 = *(const float4*)(Wout + (size_t)(n0 + arow0) * HID + ac4_0 * 4);
    if (n0 + arow1 < NCLASS) pa1 = *(const float4*)(Wout + (size_t)(n0 + arow1) * HID + ac4_1 * 4);
    float pb[4];
#pragma unroll
    for (int q = 0; q < 4; ++q) {
        int id = tid + q * 256;
        pb[q] = h[(id >> 4) * HID + (id & 15)];
    }

    int cur = 0;
    for (int kt = 0; kt < HID; kt += 16) {
        As[cur][ac4_0 * 4 + 0][arow0] = pa0.x;
        As[cur][ac4_0 * 4 + 1][arow0] = pa0.y;
        As[cur][ac4_0 * 4 + 2][arow0] = pa0.z;
        As[cur][ac4_0 * 4 + 3][arow0] = pa0.w;
        As[cur][ac4_1 * 4 + 0][arow1] = pa1.x;
        As[cur][ac4_1 * 4 + 1][arow1] = pa1.y;
        As[cur][ac4_1 * 4 + 2][arow1] = pa1.z;
        As[cur][ac4_1 * 4 + 3][arow1] = pa1.w;
#pragma unroll
        for (int q = 0; q < 4; ++q) {
            int id = tid + q * 256;
            Bs[cur][id & 15][id >> 4] = pb[q];
        }
        if (kt + 16 < HID) {
            int kn = kt + 16;
            pa0 = make_float4(0.f, 0.f, 0.f, 0.f); pa1 = pa0;
            if (n0 + arow0 < NCLASS) pa0 = *(const float4*)(Wout + (size_t)(n0 + arow0) * HID + kn + ac4_0 * 4);
            if (n0 + arow1 < NCLASS) pa1 = *(const float4*)(Wout + (size_t)(n0 + arow1) * HID + kn + ac4_1 * 4);
#pragma unroll
            for (int q = 0; q < 4; ++q) {
                int id = tid + q * 256;
                pb[q] = h[(id >> 4) * HID + kn + (id & 15)];
            }
        }
        __syncthreads();
#pragma unroll
        for (int kk = 0; kk < 16; ++kk) {
            float4 a0 = *(const float4*)&As[cur][kk][tn * 8];
            float4 a1 = *(const float4*)&As[cur][kk][tn * 8 + 4];
            float4 bv = *(const float4*)&Bs[cur][kk][tb * 4];
            unsigned long long bp0 = f4lo(bv), bp1 = f4hi(bv);
            float av[8] = {a0.x, a0.y, a0.z, a0.w, a1.x, a1.y, a1.z, a1.w};
#pragma unroll
            for (int i = 0; i < 8; ++i) {
                unsigned long long ad = pack2(av[i], av[i]);
                fma2(acc[i][0], ad, bp0);
                fma2(acc[i][1], ad, bp1);
            }
        }
        cur ^= 1;
    }

#pragma unroll
    for (int i = 0; i < 8; ++i) {
        int n = n0 + tn * 8 + i;
        if (n >= NCLASS) continue;
        float bo = bout[n];
        float2 v0 = unpack2(acc[i][0]);
        float2 v1 = unpack2(acc[i][1]);
        out[(size_t)(tb * 4 + 0) * NCLASS + n] = v0.x + bo;
        out[(size_t)(tb * 4 + 1) * NCLASS + n] = v0.y + bo;
        out[(size_t)(tb * 4 + 2) * NCLASS + n] = v1.x + bo;
        out[(size_t)(tb * 4 + 3) * NCLASS + n] = v1.y + bo;
    }
}

// ---------------- launch --------------------------------------------------------
extern "C" void kernel_launch(void* const* d_in, const int* in_sizes, int n_in,
                              void* d_out, int out_size) {
    const int*   X    = (const int*)d_in[0];
    const float* emb  = (const float*)d_in[1];
    const float* Wi   = (const float*)d_in[2];
    const float* Wh   = (const float*)d_in[3];
    const float* bi   = (const float*)d_in[4];
    const float* bh   = (const float*)d_in[5];
    // d_in[6..9]: layer-2 params — provably unused by the reference output
    const float* Wout = (const float*)d_in[10];
    const float* bout = (const float*)d_in[11];
    float* out = (float*)d_out;

    prep_kernel<<<64, 256>>>(bi, bh);
    xw_gemm_kernel<<<dim3(FOURH / 128, (STEPS * BATCH) / 128), 256>>>(X, emb, Wi);
    lstm_kernel<<<128, 256>>>(Wh);
    outproj_kernel<<<(NCLASS + 127) / 128, 256>>>(Wout, bout, out);
}

// round 5
// speedup vs baseline: 1.2317x; 1.0139x over previous
#include <cuda_runtime.h>
#include <cuda_bf16.h>
#include <cstdint>

#define EMB    512
#define HID    512
#define NCLASS 50257
#define BATCH  64
#define STEPS  256
#define FOURH  2048

// ---------------- scratch (device globals; no mallocs allowed) ---------------
__device__ float    g_xw[STEPS * BATCH * FOURH];   // 128 MiB precomputed input proj
__device__ float    g_h[2 * BATCH * HID];          // double-buffered hidden state
__device__ float    g_bsum[FOURH];                 // bi + bh
// barrier words on SEPARATE 128B L2 lines
__device__ __align__(128) unsigned g_barc[32];     // monotonic arrival counter
__device__ __align__(128) unsigned g_barp[32];     // monotonic phase

// ---------------- packed f32x2 helpers (sm_103a) ------------------------------
__device__ __forceinline__ unsigned long long pack2(float x, float y) {
    unsigned long long r;
    asm("mov.b64 %0, {%1, %2};" : "=l"(r) : "f"(x), "f"(y));
    return r;
}
__device__ __forceinline__ void fma2(unsigned long long& acc,
                                     unsigned long long a, unsigned long long b) {
    asm("fma.rn.f32x2 %0, %1, %2, %0;" : "+l"(acc) : "l"(a), "l"(b));
}
__device__ __forceinline__ float2 unpack2(unsigned long long v) {
    float2 f;
    asm("mov.b64 {%0, %1}, %2;" : "=f"(f.x), "=f"(f.y) : "l"(v));
    return f;
}
__device__ __forceinline__ float hsum2(unsigned long long v) {
    float2 f = unpack2(v);
    return f.x + f.y;
}
__device__ __forceinline__ unsigned long long f4lo(const float4& v) {
    return ((const unsigned long long*)&v)[0];
}
__device__ __forceinline__ unsigned long long f4hi(const float4& v) {
    return ((const unsigned long long*)&v)[1];
}
// fast sigmoid/tanh via MUFU (error ~2^-22, far inside tolerance)
__device__ __forceinline__ float fsigmoid_(float x) {
    return __fdividef(1.0f, 1.0f + __expf(-x));
}
__device__ __forceinline__ float ftanh_(float x) {
    return 2.0f * __fdividef(1.0f, 1.0f + __expf(-2.0f * x)) - 1.0f;
}

// ---------------- flat grid barrier (monotonic, release/acquire, no fence) ----
__device__ __forceinline__ void grid_barrier(unsigned nct, unsigned target) {
    __syncthreads();
    if (threadIdx.x == 0) {
        unsigned old;
        asm volatile("atom.release.gpu.global.add.u32 %0, [%1], 1;"
                     : "=r"(old) : "l"(&g_barc[0]) : "memory");
        if (old + 1u == target * nct) {
            asm volatile("st.release.gpu.global.u32 [%0], %1;"
                         :: "l"(&g_barp[0]), "r"(target) : "memory");
        } else {
            unsigned cur;
            do {
                asm volatile("ld.acquire.gpu.global.u32 %0, [%1];"
                             : "=r"(cur) : "l"(&g_barp[0]) : "memory");
            } while (cur < target);
        }
    }
    __syncthreads();
}

// ---------------- kernel 0: prep (bsum = bi + bh, zero h, reset barrier) ------
__global__ void prep_kernel(const float* __restrict__ bi, const float* __restrict__ bh) {
    int i = blockIdx.x * blockDim.x + threadIdx.x;
    int stride = gridDim.x * blockDim.x;
    if (i < 32) { g_barc[i] = 0u; g_barp[i] = 0u; }
    if (i < FOURH) g_bsum[i] = bi[i] + bh[i];
    for (int j = i; j < 2 * BATCH * HID; j += stride) g_h[j] = 0.0f;
}

// ---------------- kernel 1: xw = gather(emb, X) @ Wi + bsum -------------------
// C[16384, 2048], K=512. BM=BN=128, BK=16, 256 thr, 8x8 microtile, f32x2,
// register-prefetch double buffer, one sync per k-tile.
__global__ __launch_bounds__(256, 2) void xw_gemm_kernel(
    const int* __restrict__ X, const float* __restrict__ emb,
    const float* __restrict__ Wi) {
    __shared__ float As[2][16][132];  // A^T tile: As[buf][k][m]
    __shared__ float Bs[2][16][132];  // Bs[buf][k][n]
    __shared__ int   tok[128];

    const int tid = threadIdx.x;
    const int m0 = blockIdx.y * 128;
    const int n0 = blockIdx.x * 128;
    const int tm = tid >> 4, tn = tid & 15;

    const int arow0 = tid >> 2,            ac4_0 = tid & 3;
    const int arow1 = (tid + 256) >> 2,    ac4_1 = (tid + 256) & 3;
    const int bk0   = tid >> 5,            bc4_0 = tid & 31;
    const int bk1   = (tid + 256) >> 5,    bc4_1 = (tid + 256) & 31;

    if (tid < 128) {
        int m = m0 + tid;
        int b = m & 63, t = m >> 6;
        tok[tid] = X[b * STEPS + t];
    }
    __syncthreads();

    unsigned long long acc[8][4];
#pragma unroll
    for (int i = 0; i < 8; ++i)
#pragma unroll
        for (int j = 0; j < 4; ++j) acc[i][j] = 0ull;

    float4 pa0 = *(const float4*)(emb + (size_t)tok[arow0] * EMB + ac4_0 * 4);
    float4 pa1 = *(const float4*)(emb + (size_t)tok[arow1] * EMB + ac4_1 * 4);
    float4 pb0 = *(const float4*)(Wi + (size_t)bk0 * FOURH + n0 + bc4_0 * 4);
    float4 pb1 = *(const float4*)(Wi + (size_t)bk1 * FOURH + n0 + bc4_1 * 4);

    int cur = 0;
    for (int kt = 0; kt < EMB; kt += 16) {
        As[cur][ac4_0 * 4 + 0][arow0] = pa0.x;
        As[cur][ac4_0 * 4 + 1][arow0] = pa0.y;
        As[cur][ac4_0 * 4 + 2][arow0] = pa0.z;
        As[cur][ac4_0 * 4 + 3][arow0] = pa0.w;
        As[cur][ac4_1 * 4 + 0][arow1] = pa1.x;
        As[cur][ac4_1 * 4 + 1][arow1] = pa1.y;
        As[cur][ac4_1 * 4 + 2][arow1] = pa1.z;
        As[cur][ac4_1 * 4 + 3][arow1] = pa1.w;
        *(float4*)&Bs[cur][bk0][bc4_0 * 4] = pb0;
        *(float4*)&Bs[cur][bk1][bc4_1 * 4] = pb1;
        if (kt + 16 < EMB) {
            int kn = kt + 16;
            pa0 = *(const float4*)(emb + (size_t)tok[arow0] * EMB + kn + ac4_0 * 4);
            pa1 = *(const float4*)(emb + (size_t)tok[arow1] * EMB + kn + ac4_1 * 4);
            pb0 = *(const float4*)(Wi + (size_t)(kn + bk0) * FOURH + n0 + bc4_0 * 4);
            pb1 = *(const float4*)(Wi + (size_t)(kn + bk1) * FOURH + n0 + bc4_1 * 4);
        }
        __syncthreads();
#pragma unroll
        for (int kk = 0; kk < 16; ++kk) {
            float4 a0 = *(const float4*)&As[cur][kk][tm * 8];
            float4 a1 = *(const float4*)&As[cur][kk][tm * 8 + 4];
            float4 b0 = *(const float4*)&Bs[cur][kk][tn * 8];
            float4 b1 = *(const float4*)&Bs[cur][kk][tn * 8 + 4];
            unsigned long long bp0 = f4lo(b0), bp1 = f4hi(b0);
            unsigned long long bp2 = f4lo(b1), bp3 = f4hi(b1);
            float av[8] = {a0.x, a0.y, a0.z, a0.w, a1.x, a1.y, a1.z, a1.w};
#pragma unroll
            for (int i = 0; i < 8; ++i) {
                unsigned long long ad = pack2(av[i], av[i]);
                fma2(acc[i][0], ad, bp0);
                fma2(acc[i][1], ad, bp1);
                fma2(acc[i][2], ad, bp2);
                fma2(acc[i][3], ad, bp3);
            }
        }
        cur ^= 1;
    }

    const float4 bs0 = *(const float4*)&g_bsum[n0 + tn * 8];
    const float4 bs1 = *(const float4*)&g_bsum[n0 + tn * 8 + 4];
    const float bsv[8] = {bs0.x, bs0.y, bs0.z, bs0.w, bs1.x, bs1.y, bs1.z, bs1.w};
#pragma unroll
    for (int i = 0; i < 8; ++i) {
        int m = m0 + tm * 8 + i;
        float o[8];
#pragma unroll
        for (int j = 0; j < 4; ++j) {
            float2 v = unpack2(acc[i][j]);
            o[2 * j] = v.x + bsv[2 * j];
            o[2 * j + 1] = v.y + bsv[2 * j + 1];
        }
        float* orow = g_xw + (size_t)m * FOURH + n0 + tn * 8;
        *(float4*)&orow[0] = make_float4(o[0], o[1], o[2], o[3]);
        *(float4*)&orow[4] = make_float4(o[4], o[5], o[6], o[7]);
    }
}

// ---------------- kernel 2: persistent LSTM recurrence ------------------------
// 128 CTAs x 256 thr. CTA owns 4 hidden units (16 gate cols).
// 128-wide double-buffered h tiles (4 syncs/step), fast gates, flat barrier.
__global__ __launch_bounds__(256, 1) void lstm_kernel(const float* __restrict__ Wh) {
    __shared__ __align__(16) float swE[8][516];    // even gate-cols (4-bank skew)
    __shared__ __align__(16) float swO[8][516];    // odd  gate-cols
    __shared__ __align__(16) float sh[2][64][132]; // double-buffered 128-wide h tiles
    __shared__ float spre[16][65];                 // pre-activations [c][b]
    __shared__ float sc[256];                      // cell state [b*4+u]

    const int tid = threadIdx.x;
    const int cta = blockIdx.x;
    const unsigned nct = gridDim.x;

    // one-time load of the 16 Wh columns this CTA owns (col = g*512 + cta*4 + u)
    for (int i = tid; i < 16 * HID; i += 256) {
        int c = i >> 9, k = i & 511;
        int g = c >> 2, u = c & 3;
        float w = Wh[(size_t)k * FOURH + g * HID + cta * 4 + u];
        if (c & 1) swO[c >> 1][k] = w;
        else       swE[c >> 1][k] = w;
    }
    sc[tid] = 0.0f;

    const int cp = tid & 7, bp = tid >> 3;
    const int b0 = 2 * bp, b1 = b0 + 1;
    const int c0 = 2 * cp, c1 = c0 + 1;
    const int gc0 = (c0 >> 2) * HID + cta * 4 + (c0 & 3);
    const int gc1 = (c1 >> 2) * HID + cta * 4 + (c1 & 3);

    // cooperative-load mapping for 64x128 tiles: thread -> row tid>>2, 8 chunks
    const int lrow = tid >> 2;
    const int lcb  = (tid & 3) * 4;  // chunk base col (float)

    const int upd_u = tid & 3, upd_b = tid >> 2;

    __syncthreads();

    for (int t = 0; t < STEPS; ++t) {
        const float* hin  = g_h + (t & 1) * BATCH * HID;
        float*       hout = g_h + ((t + 1) & 1) * BATCH * HID;
        const float* xwt  = g_xw + (size_t)t * BATCH * FOURH;

        // prefetch xw gate biases for this step (DRAM; hidden behind the GEMM)
        float x00 = __ldcs(&xwt[b0 * FOURH + gc0]);
        float x01 = __ldcs(&xwt[b0 * FOURH + gc1]);
        float x10 = __ldcs(&xwt[b1 * FOURH + gc0]);
        float x11 = __ldcs(&xwt[b1 * FOURH + gc1]);

        unsigned long long a00a = 0, a00b = 0, a01a = 0, a01b = 0;
        unsigned long long a10a = 0, a10b = 0, a11a = 0, a11b = 0;

        float4 p[8];
        // tile 0 (k 0..127) -> regs -> sh[0]
#pragma unroll
        for (int j = 0; j < 8; ++j)
            p[j] = __ldcg((const float4*)(hin + lrow * HID + lcb + j * 16));
#pragma unroll
        for (int j = 0; j < 8; ++j)
            *(float4*)&sh[0][lrow][lcb + j * 16] = p[j];
        // prefetch tile 1 (k 128..255)
#pragma unroll
        for (int j = 0; j < 8; ++j)
            p[j] = __ldcg((const float4*)(hin + lrow * HID + 128 + lcb + j * 16));
        __syncthreads();

        for (int kt4 = 0; kt4 < 4; ++kt4) {
            const float* shb = &sh[kt4 & 1][0][0];
            const float* hrow0 = shb + b0 * 132;
            const float* hrow1 = shb + b1 * 132;
            const float* wrow0 = &swE[cp][kt4 * 128];
            const float* wrow1 = &swO[cp][kt4 * 128];
#pragma unroll 8
            for (int kk = 0; kk < 128; kk += 4) {
                float4 h0 = *(const float4*)(hrow0 + kk);
                float4 h1 = *(const float4*)(hrow1 + kk);
                float4 w0 = *(const float4*)(wrow0 + kk);
                float4 w1 = *(const float4*)(wrow1 + kk);
                unsigned long long h0a = f4lo(h0), h0b = f4hi(h0);
                unsigned long long h1a = f4lo(h1), h1b = f4hi(h1);
                unsigned long long w0a = f4lo(w0), w0b = f4hi(w0);
                unsigned long long w1a = f4lo(w1), w1b = f4hi(w1);
                fma2(a00a, h0a, w0a); fma2(a00b, h0b, w0b);
                fma2(a01a, h0a, w1a); fma2(a01b, h0b, w1b);
                fma2(a10a, h1a, w0a); fma2(a10b, h1b, w0b);
                fma2(a11a, h1a, w1a); fma2(a11b, h1b, w1b);
            }
            if (kt4 < 3) {
                int nb = (kt4 + 1) & 1;
#pragma unroll
                for (int j = 0; j < 8; ++j)
                    *(float4*)&sh[nb][lrow][lcb + j * 16] = p[j];
                if (kt4 < 2) {
                    int ko = (kt4 + 2) * 128;
#pragma unroll
                    for (int j = 0; j < 8; ++j)
                        p[j] = __ldcg((const float4*)(hin + lrow * HID + ko + lcb + j * 16));
                }
                __syncthreads();
            }
        }

        spre[c0][b0] = hsum2(a00a) + hsum2(a00b) + x00;
        spre[c1][b0] = hsum2(a01a) + hsum2(a01b) + x01;
        spre[c0][b1] = hsum2(a10a) + hsum2(a10b) + x10;
        spre[c1][b1] = hsum2(a11a) + hsum2(a11b) + x11;
        __syncthreads();

        // cell update: thread -> (b = tid>>2, u = tid&3)
        {
            float pi = spre[0  + upd_u][upd_b];
            float pf = spre[4  + upd_u][upd_b];
            float pg = spre[8  + upd_u][upd_b];
            float po = spre[12 + upd_u][upd_b];
            float ig = fsigmoid_(pi);
            float fg = fsigmoid_(pf);
            float gg = ftanh_(pg);
            float og = fsigmoid_(po);
            float cc = fg * sc[tid] + ig * gg;
            sc[tid] = cc;
            float hh = og * ftanh_(cc);
            __stcg(&hout[upd_b * HID + cta * 4 + upd_u], hh);
        }
        grid_barrier(nct, (unsigned)(t + 1));
    }
}

// ---------------- kernel 3: out = h_final @ Wout^T + bout ---------------------
// BM=64, 786 CTAs, occ 4. 256 thr, 4n x 4b microtile, double-buffered.
__global__ __launch_bounds__(256, 4) void outproj_kernel(
    const float* __restrict__ Wout, const float* __restrict__ bout,
    float* __restrict__ out) {
    __shared__ float As[2][16][68];  // Wout^T tile: As[buf][k][n_local]
    __shared__ float Bs[2][16][68];  // h^T tile:   Bs[buf][k][b]

    const int tid = threadIdx.x;
    const int n0 = blockIdx.x * 64;
    const int tn = tid & 15, tb = tid >> 4;
    const float* h = g_h;  // final h lives in buffer 0 (STEPS even)

    const int arow = tid >> 2, ac4 = tid & 3;  // As loader: row 0..63, k-quad
    // Bs loader uses same mapping: b-row tid>>2, k-quad tid&3

    unsigned long long acc[4][2];
#pragma unroll
    for (int i = 0; i < 4; ++i) { acc[i][0] = 0ull; acc[i][1] = 0ull; }

    float4 pa = make_float4(0.f, 0.f, 0.f, 0.f);
    if (n0 + arow < NCLASS) pa = *(const float4*)(Wout + (size_t)(n0 + arow) * HID + ac4 * 4);
    float4 pbv = *(const float4*)(h + arow * HID + ac4 * 4);

    int cur = 0;
    for (int kt = 0; kt < HID; kt += 16) {
        As[cur][ac4 * 4 + 0][arow] = pa.x;
        As[cur][ac4 * 4 + 1][arow] = pa.y;
        As[cur][ac4 * 4 + 2][arow] = pa.z;
        As[cur][ac4 * 4 + 3][arow] = pa.w;
        Bs[cur][ac4 * 4 + 0][arow] = pbv.x;
        Bs[cur][ac4 * 4 + 1][arow] = pbv.y;
        Bs[cur][ac4 * 4 + 2][arow] = pbv.z;
        Bs[cur][ac4 * 4 + 3][arow] = pbv.w;
        if (kt + 16 < HID) {
            int kn = kt + 16;
            pa = make_float4(0.f, 0.f, 0.f, 0.f);
            if (n0 + arow < NCLASS) pa = *(const float4*)(Wout + (size_t)(n0 + arow) * HID + kn + ac4 * 4);
            pbv = *(const float4*)(h + arow * HID + kn + ac4 * 4);
        }
        __syncthreads();
#pragma unroll
        for (int kk = 0; kk < 16; ++kk) {
            float4 av = *(const float4*)&As[cur][kk][tn * 4];
            float4 bv = *(const float4*)&Bs[cur][kk][tb * 4];
            unsigned long long bp0 = f4lo(bv), bp1 = f4hi(bv);
            float avv[4] = {av.x, av.y, av.z, av.w};
#pragma unroll
            for (int i = 0; i < 4; ++i) {
                unsigned long long ad = pack2(avv[i], avv[i]);
                fma2(acc[i][0], ad, bp0);
                fma2(acc[i][1], ad, bp1);
            }
        }
        cur ^= 1;
    }

#pragma unroll
    for (int i = 0; i < 4; ++i) {
        int n = n0 + tn * 4 + i;
        if (n >= NCLASS) continue;
        float bo = bout[n];
        float2 v0 = unpack2(acc[i][0]);
        float2 v1 = unpack2(acc[i][1]);
        out[(size_t)(tb * 4 + 0) * NCLASS + n] = v0.x + bo;
        out[(size_t)(tb * 4 + 1) * NCLASS + n] = v0.y + bo;
        out[(size_t)(tb * 4 + 2) * NCLASS + n] = v1.x + bo;
        out[(size_t)(tb * 4 + 3) * NCLASS + n] = v1.y + bo;
    }
}

// ---------------- launch --------------------------------------------------------
extern "C" void kernel_launch(void* const* d_in, const int* in_sizes, int n_in,
                              void* d_out, int out_size) {
    const int*   X    = (const int*)d_in[0];
    const float* emb  = (const float*)d_in[1];
    const float* Wi   = (const float*)d_in[2];
    const float* Wh   = (const float*)d_in[3];
    const float* bi   = (const float*)d_in[4];
    const float* bh   = (const float*)d_in[5];
    // d_in[6..9]: layer-2 params — provably unused by the reference output
    const float* Wout = (const float*)d_in[10];
    const float* bout = (const float*)d_in[11];
    float* out = (float*)d_out;

    prep_kernel<<<64, 256>>>(bi, bh);
    xw_gemm_kernel<<<dim3(FOURH / 128, (STEPS * BATCH) / 128), 256>>>(X, emb, Wi);
    lstm_kernel<<<128, 256>>>(Wh);
    outproj_kernel<<<(NCLASS + 63) / 64, 256>>>(Wout, bout, out);
}

// round 6
// speedup vs baseline: 1.5106x; 1.2265x over previous
#include <cuda_runtime.h>
#include <cuda_bf16.h>
#include <cstdint>

#define EMB    512
#define HID    512
#define NCLASS 50257
#define BATCH  64
#define STEPS  256
#define FOURH  2048

// ---------------- scratch (device globals; no mallocs allowed) ---------------
__device__ float    g_xw[STEPS * BATCH * FOURH];   // 128 MiB precomputed input proj
__device__ float    g_h[2 * BATCH * HID];          // double-buffered hidden state
__device__ float    g_bsum[FOURH];                 // bi + bh
// barrier words on SEPARATE 128B L2 lines
__device__ __align__(128) unsigned g_barc[32];     // monotonic arrival counter
__device__ __align__(128) unsigned g_barp[32];     // monotonic phase

// ---------------- packed f32x2 helpers (sm_103a) ------------------------------
__device__ __forceinline__ unsigned long long pack2(float x, float y) {
    unsigned long long r;
    asm("mov.b64 %0, {%1, %2};" : "=l"(r) : "f"(x), "f"(y));
    return r;
}
__device__ __forceinline__ void fma2(unsigned long long& acc,
                                     unsigned long long a, unsigned long long b) {
    asm("fma.rn.f32x2 %0, %1, %2, %0;" : "+l"(acc) : "l"(a), "l"(b));
}
__device__ __forceinline__ float2 unpack2(unsigned long long v) {
    float2 f;
    asm("mov.b64 {%0, %1}, %2;" : "=f"(f.x), "=f"(f.y) : "l"(v));
    return f;
}
__device__ __forceinline__ float hsum2(unsigned long long v) {
    float2 f = unpack2(v);
    return f.x + f.y;
}
__device__ __forceinline__ unsigned long long f4lo(const float4& v) {
    return ((const unsigned long long*)&v)[0];
}
__device__ __forceinline__ unsigned long long f4hi(const float4& v) {
    return ((const unsigned long long*)&v)[1];
}
__device__ __forceinline__ float fsigmoid_(float x) {
    return __fdividef(1.0f, 1.0f + __expf(-x));
}
__device__ __forceinline__ float ftanh_(float x) {
    return 2.0f * __fdividef(1.0f, 1.0f + __expf(-2.0f * x)) - 1.0f;
}
// cp.async 16B, L2-only (.cg) — coherent across the grid barrier, no L1 staleness
__device__ __forceinline__ void cpasync16(unsigned dst, const void* src) {
    asm volatile("cp.async.cg.shared.global [%0], [%1], 16;"
                 :: "r"(dst), "l"(src) : "memory");
}

// ---------------- flat grid barrier (monotonic, release/acquire) --------------
__device__ __forceinline__ void grid_barrier(unsigned nct, unsigned target) {
    __syncthreads();
    if (threadIdx.x == 0) {
        unsigned old;
        asm volatile("atom.release.gpu.global.add.u32 %0, [%1], 1;"
                     : "=r"(old) : "l"(&g_barc[0]) : "memory");
        if (old + 1u == target * nct) {
            asm volatile("st.release.gpu.global.u32 [%0], %1;"
                         :: "l"(&g_barp[0]), "r"(target) : "memory");
        } else {
            unsigned cur;
            do {
                asm volatile("ld.acquire.gpu.global.u32 %0, [%1];"
                             : "=r"(cur) : "l"(&g_barp[0]) : "memory");
            } while (cur < target);
        }
    }
    __syncthreads();
}

// ---------------- kernel 0: prep (bsum = bi + bh, zero h, reset barrier) ------
__global__ void prep_kernel(const float* __restrict__ bi, const float* __restrict__ bh) {
    int i = blockIdx.x * blockDim.x + threadIdx.x;
    int stride = gridDim.x * blockDim.x;
    if (i < 32) { g_barc[i] = 0u; g_barp[i] = 0u; }
    if (i < FOURH) g_bsum[i] = bi[i] + bh[i];
    for (int j = i; j < 2 * BATCH * HID; j += stride) g_h[j] = 0.0f;
}

// ---------------- kernel 1: xw = gather(emb, X) @ Wi + bsum -------------------
__global__ __launch_bounds__(256, 2) void xw_gemm_kernel(
    const int* __restrict__ X, const float* __restrict__ emb,
    const float* __restrict__ Wi) {
    __shared__ float As[2][16][132];
    __shared__ float Bs[2][16][132];
    __shared__ int   tok[128];

    const int tid = threadIdx.x;
    const int m0 = blockIdx.y * 128;
    const int n0 = blockIdx.x * 128;
    const int tm = tid >> 4, tn = tid & 15;

    const int arow0 = tid >> 2,            ac4_0 = tid & 3;
    const int arow1 = (tid + 256) >> 2,    ac4_1 = (tid + 256) & 3;
    const int bk0   = tid >> 5,            bc4_0 = tid & 31;
    const int bk1   = (tid + 256) >> 5,    bc4_1 = (tid + 256) & 31;

    if (tid < 128) {
        int m = m0 + tid;
        int b = m & 63, t = m >> 6;
        tok[tid] = X[b * STEPS + t];
    }
    __syncthreads();

    unsigned long long acc[8][4];
#pragma unroll
    for (int i = 0; i < 8; ++i)
#pragma unroll
        for (int j = 0; j < 4; ++j) acc[i][j] = 0ull;

    float4 pa0 = *(const float4*)(emb + (size_t)tok[arow0] * EMB + ac4_0 * 4);
    float4 pa1 = *(const float4*)(emb + (size_t)tok[arow1] * EMB + ac4_1 * 4);
    float4 pb0 = *(const float4*)(Wi + (size_t)bk0 * FOURH + n0 + bc4_0 * 4);
    float4 pb1 = *(const float4*)(Wi + (size_t)bk1 * FOURH + n0 + bc4_1 * 4);

    int cur = 0;
    for (int kt = 0; kt < EMB; kt += 16) {
        As[cur][ac4_0 * 4 + 0][arow0] = pa0.x;
        As[cur][ac4_0 * 4 + 1][arow0] = pa0.y;
        As[cur][ac4_0 * 4 + 2][arow0] = pa0.z;
        As[cur][ac4_0 * 4 + 3][arow0] = pa0.w;
        As[cur][ac4_1 * 4 + 0][arow1] = pa1.x;
        As[cur][ac4_1 * 4 + 1][arow1] = pa1.y;
        As[cur][ac4_1 * 4 + 2][arow1] = pa1.z;
        As[cur][ac4_1 * 4 + 3][arow1] = pa1.w;
        *(float4*)&Bs[cur][bk0][bc4_0 * 4] = pb0;
        *(float4*)&Bs[cur][bk1][bc4_1 * 4] = pb1;
        if (kt + 16 < EMB) {
            int kn = kt + 16;
            pa0 = *(const float4*)(emb + (size_t)tok[arow0] * EMB + kn + ac4_0 * 4);
            pa1 = *(const float4*)(emb + (size_t)tok[arow1] * EMB + kn + ac4_1 * 4);
            pb0 = *(const float4*)(Wi + (size_t)(kn + bk0) * FOURH + n0 + bc4_0 * 4);
            pb1 = *(const float4*)(Wi + (size_t)(kn + bk1) * FOURH + n0 + bc4_1 * 4);
        }
        __syncthreads();
#pragma unroll
        for (int kk = 0; kk < 16; ++kk) {
            float4 a0 = *(const float4*)&As[cur][kk][tm * 8];
            float4 a1 = *(const float4*)&As[cur][kk][tm * 8 + 4];
            float4 b0 = *(const float4*)&Bs[cur][kk][tn * 8];
            float4 b1 = *(const float4*)&Bs[cur][kk][tn * 8 + 4];
            unsigned long long bp0 = f4lo(b0), bp1 = f4hi(b0);
            unsigned long long bp2 = f4lo(b1), bp3 = f4hi(b1);
            float av[8] = {a0.x, a0.y, a0.z, a0.w, a1.x, a1.y, a1.z, a1.w};
#pragma unroll
            for (int i = 0; i < 8; ++i) {
                unsigned long long ad = pack2(av[i], av[i]);
                fma2(acc[i][0], ad, bp0);
                fma2(acc[i][1], ad, bp1);
                fma2(acc[i][2], ad, bp2);
                fma2(acc[i][3], ad, bp3);
            }
        }
        cur ^= 1;
    }

    const float4 bs0 = *(const float4*)&g_bsum[n0 + tn * 8];
    const float4 bs1 = *(const float4*)&g_bsum[n0 + tn * 8 + 4];
    const float bsv[8] = {bs0.x, bs0.y, bs0.z, bs0.w, bs1.x, bs1.y, bs1.z, bs1.w};
#pragma unroll
    for (int i = 0; i < 8; ++i) {
        int m = m0 + tm * 8 + i;
        float o[8];
#pragma unroll
        for (int j = 0; j < 4; ++j) {
            float2 v = unpack2(acc[i][j]);
            o[2 * j] = v.x + bsv[2 * j];
            o[2 * j + 1] = v.y + bsv[2 * j + 1];
        }
        float* orow = g_xw + (size_t)m * FOURH + n0 + tn * 8;
        *(float4*)&orow[0] = make_float4(o[0], o[1], o[2], o[3]);
        *(float4*)&orow[4] = make_float4(o[4], o[5], o[6], o[7]);
    }
}

// ---------------- kernel 2: persistent LSTM, smem-traffic-minimal -------------
// 128 CTAs x 256 thr. CTA owns 16 gate-cols. Lane = (col 0..15, k-quad 0..1);
// warp owns 8 batches. W stationary per lane (coalesced LDS.128);
// h read via LDS broadcast (free); h staged per step with cp.async.cg.
// Dynamic smem: w_s[64][32][4] | h_s[64][512] | spre[16][65]
__global__ __launch_bounds__(256, 1) void lstm_kernel(const float* __restrict__ Wh) {
    extern __shared__ __align__(16) float sm[];
    float* w_s  = sm;                    // 8192 floats (32 KB)
    float* h_s  = sm + 8192;             // 32768 floats (128 KB)
    float* spre = sm + 8192 + 32768;     // 16*65 floats

    const int tid = threadIdx.x;
    const int cta = blockIdx.x;
    const unsigned nct = gridDim.x;
    const int lane = tid & 31, wrp = tid >> 5;

    // one-time: rearrange this CTA's 16 Wh columns into per-lane layout
    // w_s[it*128 + ln*4 + j] = Wh[k = it*8 + (ln>>4)*4 + j][gcol(ln&15)]
    for (int i = tid; i < 8192; i += 256) {
        int j  = i & 3;
        int ln = (i >> 2) & 31;
        int it = i >> 7;
        int c  = ln & 15;
        int k  = it * 8 + (ln >> 4) * 4 + j;
        int gcol = (c >> 2) * HID + cta * 4 + (c & 3);
        w_s[i] = Wh[(size_t)k * FOURH + gcol];
    }

    const int col = lane & 15, kq = lane >> 4;
    const int ub = tid >> 2, uu = tid & 3;     // update mapping: batch, unit
    float creg = 0.0f;                          // cell state lives in a register

    const unsigned hs_u32 = (unsigned)__cvta_generic_to_shared(h_s);
    const float* hrow = h_s + wrp * 8 * HID + kq * 4;
    const float* wp   = w_s + lane * 4;

    __syncthreads();

    for (int t = 0; t < STEPS; ++t) {
        const float* hin  = g_h + (t & 1) * BATCH * HID;
        float*       hout = g_h + ((t + 1) & 1) * BATCH * HID;
        const float* xwt  = g_xw + (size_t)t * BATCH * FOURH
                            + (size_t)ub * FOURH + cta * 4 + uu;

        // prefetch this step's xw gate biases (DRAM, hidden behind staging+GEMM)
        float x0 = __ldcs(xwt);
        float x1 = __ldcs(xwt + 512);
        float x2 = __ldcs(xwt + 1024);
        float x3 = __ldcs(xwt + 1536);

        // stage h[64][512] into smem via cp.async.cg (bypasses L1 -> coherent)
#pragma unroll
        for (int j = 0; j < 32; ++j) {
            int i = tid + j * 256;                   // float4 index 0..8191
            cpasync16(hs_u32 + i * 16, hin + i * 4);
        }
        asm volatile("cp.async.commit_group;");
        asm volatile("cp.async.wait_group 0;" ::: "memory");
        __syncthreads();

        // GEMM: acc[j] over this lane's 4-k quad, j = batch within warp
        unsigned long long acc[8];
#pragma unroll
        for (int j = 0; j < 8; ++j) acc[j] = 0ull;

#pragma unroll 4
        for (int it = 0; it < 64; ++it) {
            float4 wv = *(const float4*)(wp + it * 128);
            unsigned long long w0 = f4lo(wv), w1 = f4hi(wv);
#pragma unroll
            for (int j = 0; j < 8; ++j) {
                float4 hv = *(const float4*)(hrow + j * HID + it * 8);  // broadcast
                fma2(acc[j], f4lo(hv), w0);
                fma2(acc[j], f4hi(hv), w1);
            }
        }

        // reduce the two k-halves (lane ^ 16) and write pre-activations
        float part[8];
#pragma unroll
        for (int j = 0; j < 8; ++j) {
            float p = hsum2(acc[j]);
            p += __shfl_xor_sync(0xffffffffu, p, 16);
            part[j] = p;
        }
        if (kq == 0) {
#pragma unroll
            for (int j = 0; j < 8; ++j)
                spre[col * 65 + wrp * 8 + j] = part[j];
        }
        __syncthreads();

        // cell update: thread -> (b = tid>>2, u = tid&3); c in register
        {
            float pi = spre[(0  + uu) * 65 + ub] + x0;
            float pf = spre[(4  + uu) * 65 + ub] + x1;
            float pg = spre[(8  + uu) * 65 + ub] + x2;
            float po = spre[(12 + uu) * 65 + ub] + x3;
            float ig = fsigmoid_(pi);
            float fg = fsigmoid_(pf);
            float gg = ftanh_(pg);
            float og = fsigmoid_(po);
            creg = fg * creg + ig * gg;
            float hh = og * ftanh_(creg);
            __stcg(&hout[ub * HID + cta * 4 + uu], hh);
        }
        grid_barrier(nct, (unsigned)(t + 1));
    }
}

#define SMEM_LSTM ((8192 + 32768 + 16 * 65) * 4)

// ---------------- kernel 3: out = h_final @ Wout^T + bout ---------------------
__global__ __launch_bounds__(256, 4) void outproj_kernel(
    const float* __restrict__ Wout, const float* __restrict__ bout,
    float* __restrict__ out) {
    __shared__ float As[2][16][68];
    __shared__ float Bs[2][16][68];

    const int tid = threadIdx.x;
    const int n0 = blockIdx.x * 64;
    const int tn = tid & 15, tb = tid >> 4;
    const float* h = g_h;  // final h lives in buffer 0 (STEPS even)

    const int arow = tid >> 2, ac4 = tid & 3;

    unsigned long long acc[4][2];
#pragma unroll
    for (int i = 0; i < 4; ++i) { acc[i][0] = 0ull; acc[i][1] = 0ull; }

    float4 pa = make_float4(0.f, 0.f, 0.f, 0.f);
    if (n0 + arow < NCLASS) pa = *(const float4*)(Wout + (size_t)(n0 + arow) * HID + ac4 * 4);
    float4 pbv = *(const float4*)(h + arow * HID + ac4 * 4);

    int cur = 0;
    for (int kt = 0; kt < HID; kt += 16) {
        As[cur][ac4 * 4 + 0][arow] = pa.x;
        As[cur][ac4 * 4 + 1][arow] = pa.y;
        As[cur][ac4 * 4 + 2][arow] = pa.z;
        As[cur][ac4 * 4 + 3][arow] = pa.w;
        Bs[cur][ac4 * 4 + 0][arow] = pbv.x;
        Bs[cur][ac4 * 4 + 1][arow] = pbv.y;
        Bs[cur][ac4 * 4 + 2][arow] = pbv.z;
        Bs[cur][ac4 * 4 + 3][arow] = pbv.w;
        if (kt + 16 < HID) {
            int kn = kt + 16;
            pa = make_float4(0.f, 0.f, 0.f, 0.f);
            if (n0 + arow < NCLASS) pa = *(const float4*)(Wout + (size_t)(n0 + arow) * HID + kn + ac4 * 4);
            pbv = *(const float4*)(h + arow * HID + kn + ac4 * 4);
        }
        __syncthreads();
#pragma unroll
        for (int kk = 0; kk < 16; ++kk) {
            float4 av = *(const float4*)&As[cur][kk][tn * 4];
            float4 bv = *(const float4*)&Bs[cur][kk][tb * 4];
            unsigned long long bp0 = f4lo(bv), bp1 = f4hi(bv);
            float avv[4] = {av.x, av.y, av.z, av.w};
#pragma unroll
            for (int i = 0; i < 4; ++i) {
                unsigned long long ad = pack2(avv[i], avv[i]);
                fma2(acc[i][0], ad, bp0);
                fma2(acc[i][1], ad, bp1);
            }
        }
        cur ^= 1;
    }

#pragma unroll
    for (int i = 0; i < 4; ++i) {
        int n = n0 + tn * 4 + i;
        if (n >= NCLASS) continue;
        float bo = bout[n];
        float2 v0 = unpack2(acc[i][0]);
        float2 v1 = unpack2(acc[i][1]);
        out[(size_t)(tb * 4 + 0) * NCLASS + n] = v0.x + bo;
        out[(size_t)(tb * 4 + 1) * NCLASS + n] = v0.y + bo;
        out[(size_t)(tb * 4 + 2) * NCLASS + n] = v1.x + bo;
        out[(size_t)(tb * 4 + 3) * NCLASS + n] = v1.y + bo;
    }
}

// ---------------- launch --------------------------------------------------------
extern "C" void kernel_launch(void* const* d_in, const int* in_sizes, int n_in,
                              void* d_out, int out_size) {
    const int*   X    = (const int*)d_in[0];
    const float* emb  = (const float*)d_in[1];
    const float* Wi   = (const float*)d_in[2];
    const float* Wh   = (const float*)d_in[3];
    const float* bi   = (const float*)d_in[4];
    const float* bh   = (const float*)d_in[5];
    // d_in[6..9]: layer-2 params — provably unused by the reference output
    const float* Wout = (const float*)d_in[10];
    const float* bout = (const float*)d_in[11];
    float* out = (float*)d_out;

    // allow >48KB dynamic smem (attribute set, not an allocation; idempotent)
    cudaFuncSetAttribute(lstm_kernel,
                         cudaFuncAttributeMaxDynamicSharedMemorySize, SMEM_LSTM);

    prep_kernel<<<64, 256>>>(bi, bh);
    xw_gemm_kernel<<<dim3(FOURH / 128, (STEPS * BATCH) / 128), 256>>>(X, emb, Wi);
    lstm_kernel<<<128, 256, SMEM_LSTM>>>(Wh);
    outproj_kernel<<<(NCLASS + 63) / 64, 256>>>(Wout, bout, out);
}